// round 1
// baseline (speedup 1.0000x reference)
#include <cuda_runtime.h>

// Positional encoding: out[n, c, {sin,cos}, d] = trig(x[n,c] * 2^d), d=0..9, c=0..2.
// Row = 60 f32 = 15 float4. One thread per output float4 -> perfectly coalesced STG.128.
// Entry e in 0..59: c=e/20, r=e%20, iscos=(r>=10), d=r%10.
// Uniform (divergence-free) evaluation: sin(x*2^d + iscos*pi/2).

#define HALF_PI 1.57079632679489662f

__global__ void __launch_bounds__(256) pe_kernel(const float* __restrict__ x,
                                                 float4* __restrict__ out,
                                                 int total /* = N*15 */) {
    int t = blockIdx.x * blockDim.x + threadIdx.x;
    if (t >= total) return;

    int n = t / 15;        // row
    int k = t - n * 15;    // float4 slot within row, 0..14
    int c = k / 5;         // channel 0..2  (20 floats = 5 float4 per channel)
    int j = k - c * 5;     // float4 slot within channel block, 0..4

    float xv = __ldg(&x[n * 3 + c]);

    int r0 = 4 * j;        // entry index within the 20-float channel block
    float vals[4];
#pragma unroll
    for (int m = 0; m < 4; ++m) {
        int r = r0 + m;                 // 0..19
        int iscos = (r >= 10) ? 1 : 0;  // first 10 = sin, last 10 = cos
        int d = r - 10 * iscos;         // frequency exponent 0..9
        float scale = __int_as_float((127 + d) << 23);  // exact 2^d
        float phase = xv * scale;                        // exact vs reference fp32 phase
        float arg = iscos ? (phase + HALF_PI) : phase;   // cos(p) = sin(p + pi/2)
        vals[m] = __sinf(arg);
    }

    float4 v;
    v.x = vals[0]; v.y = vals[1]; v.z = vals[2]; v.w = vals[3];
    out[t] = v;
}

extern "C" void kernel_launch(void* const* d_in, const int* in_sizes, int n_in,
                              void* d_out, int out_size) {
    const float* x = (const float*)d_in[0];
    float4* out = (float4*)d_out;
    int n_rows = in_sizes[0] / 3;       // x is [N, 3]
    int total = n_rows * 15;            // float4 slots (N * 60 / 4)
    int threads = 256;
    int blocks = (total + threads - 1) / threads;
    pe_kernel<<<blocks, threads>>>(x, out, total);
}

// round 8
// speedup vs baseline: 1.2589x; 1.2589x over previous
#include <cuda_runtime.h>

// Positional encoding: out[n, c, {sin,cos}, d] = trig(x[n,c] * 2^d), d=0..9, c=0..2.
// Row = 60 f32 = 15 float4. One float4 per thread-iteration, grid-stride loop with
// stride % 15 == 0 so the slot decomposition (t mod 15) is loop-invariant and hoisted.
// Each element: sin(fma(x, 2^d, off)), off = 0 (sin half) or pi/2 (cos half).

#define HALF_PI 1.57079632679489662f

__global__ void __launch_bounds__(256) pe_kernel(const float* __restrict__ x,
                                                 float4* __restrict__ out,
                                                 int total /* N*15 */,
                                                 int stride /* gridDim*blockDim, %15==0 */) {
    int t0 = blockIdx.x * blockDim.x + threadIdx.x;

    // Loop-invariant slot decomposition (stride % 15 == 0 keeps k fixed).
    int k = t0 % 15;       // float4 slot within row
    int c = k / 5;         // channel 0..2
    int j = k - c * 5;     // float4 within channel block

    float scale[4], off[4];
#pragma unroll
    for (int m = 0; m < 4; ++m) {
        int r = 4 * j + m;              // 0..19 within channel block
        int iscos = (r >= 10) ? 1 : 0;  // first 10 sin, last 10 cos
        int d = r - 10 * iscos;         // frequency exponent 0..9
        scale[m] = __int_as_float((127 + d) << 23);  // exact 2^d
        off[m] = iscos ? HALF_PI : 0.0f;             // cos(p) = sin(p + pi/2)
    }

    int xi = (t0 / 15) * 3 + c;          // x index for this thread's first slot
    const int xstep = (stride / 15) * 3; // rows advance by stride/15 per iteration

    for (int t = t0; t < total; t += stride, xi += xstep) {
        float xv = __ldg(&x[xi]);
        float4 v;
        v.x = __sinf(fmaf(xv, scale[0], off[0]));
        v.y = __sinf(fmaf(xv, scale[1], off[1]));
        v.z = __sinf(fmaf(xv, scale[2], off[2]));
        v.w = __sinf(fmaf(xv, scale[3], off[3]));
        __stcs(&out[t], v);   // streaming store: don't pollute L2 with 480MB
    }
}

extern "C" void kernel_launch(void* const* d_in, const int* in_sizes, int n_in,
                              void* d_out, int out_size) {
    const float* x = (const float*)d_in[0];
    float4* out = (float4*)d_out;
    int n_rows = in_sizes[0] / 3;   // x is [N, 3]
    int total = n_rows * 15;        // float4 slots

    const int threads = 256;
    // blocks must be a multiple of 15 so stride % 15 == 0 (256 % 15 == 1).
    // 1110 = 148 SMs * 7.5 -> ~7-8 blocks/SM, ~106 loop iterations per thread.
    int blocks = 1110;
    int stride = blocks * threads;
    pe_kernel<<<blocks, threads>>>(x, out, total, stride);
}

// round 10
// speedup vs baseline: 1.2593x; 1.0004x over previous
#include <cuda_runtime.h>

// Positional encoding: out[n, c, {sin,cos}, d] = trig(x[n,c] * 2^d), d=0..9, c=0..2.
// Row = 60 f32 = 15 float4. Grid-stride loop, stride % 15 == 0 so the slot
// decomposition (t mod 15) is loop-invariant. Unrolled x2 (loop step 2*stride,
// both slots share the same k) to double load/store MLP per warp:
// batch 2 LDGs -> compute -> 2 back-to-back STG.128.

#define HALF_PI 1.57079632679489662f

__global__ void __launch_bounds__(256) pe_kernel(const float* __restrict__ x,
                                                 float4* __restrict__ out,
                                                 int total /* N*15 */,
                                                 int stride /* gridDim*blockDim, %15==0 */) {
    int t0 = blockIdx.x * blockDim.x + threadIdx.x;

    // Loop-invariant slot decomposition.
    int k = t0 % 15;       // float4 slot within row
    int c = k / 5;         // channel 0..2
    int j = k - c * 5;     // float4 within channel block

    float scale[4], off[4];
#pragma unroll
    for (int m = 0; m < 4; ++m) {
        int r = 4 * j + m;              // 0..19 within channel block
        int iscos = (r >= 10) ? 1 : 0;  // first 10 sin, last 10 cos
        int d = r - 10 * iscos;         // frequency exponent 0..9
        scale[m] = __int_as_float((127 + d) << 23);  // exact 2^d
        off[m] = iscos ? HALF_PI : 0.0f;             // cos(p) = sin(p + pi/2)
    }

    int xi = (t0 / 15) * 3 + c;          // x index for slot t
    const int xstep = (stride / 15) * 3; // x advance per `stride` slots
    const int stride2 = 2 * stride;
    const int xstep2 = 2 * xstep;

    int t = t0;
    // Main loop: two slots per iteration (same k), batched loads then batched stores.
    for (; t + stride < total; t += stride2, xi += xstep2) {
        float xa = __ldg(&x[xi]);
        float xb = __ldg(&x[xi + xstep]);

        float4 va, vb;
        va.x = __sinf(fmaf(xa, scale[0], off[0]));
        va.y = __sinf(fmaf(xa, scale[1], off[1]));
        va.z = __sinf(fmaf(xa, scale[2], off[2]));
        va.w = __sinf(fmaf(xa, scale[3], off[3]));
        vb.x = __sinf(fmaf(xb, scale[0], off[0]));
        vb.y = __sinf(fmaf(xb, scale[1], off[1]));
        vb.z = __sinf(fmaf(xb, scale[2], off[2]));
        vb.w = __sinf(fmaf(xb, scale[3], off[3]));

        __stcs(&out[t], va);
        __stcs(&out[t + stride], vb);
    }
    // Tail: at most one remaining slot for this thread.
    if (t < total) {
        float xv = __ldg(&x[xi]);
        float4 v;
        v.x = __sinf(fmaf(xv, scale[0], off[0]));
        v.y = __sinf(fmaf(xv, scale[1], off[1]));
        v.z = __sinf(fmaf(xv, scale[2], off[2]));
        v.w = __sinf(fmaf(xv, scale[3], off[3]));
        __stcs(&out[t], v);
    }
}

extern "C" void kernel_launch(void* const* d_in, const int* in_sizes, int n_in,
                              void* d_out, int out_size) {
    const float* x = (const float*)d_in[0];
    float4* out = (float4*)d_out;
    int n_rows = in_sizes[0] / 3;   // x is [N, 3]
    int total = n_rows * 15;        // float4 slots

    const int threads = 256;
    // blocks must be a multiple of 15 so stride % 15 == 0.
    // 1110 = 148 SMs * 7.5 -> ~7-8 blocks/SM, ~53 unrolled iterations per thread.
    int blocks = 1110;
    int stride = blocks * threads;
    pe_kernel<<<blocks, threads>>>(x, out, total, stride);
}